// round 1
// baseline (speedup 1.0000x reference)
#include <cuda_runtime.h>
#include <math.h>

// ---------------- problem constants ----------------
#define NB      8
#define HEADS   12
#define DIMM    768
#define HDD     64
#define TMAX    197
#define NPATCH  196
#define FFD     3072
#define NCLS    1000
#define MINTOK  16
#define SCALE_  0.125f   // HD^-0.5 = 1/8

// ---------------- device scratch (no allocation allowed) ----------------
__device__ float g_X  [NB*TMAX*DIMM];
__device__ float g_X2 [NB*TMAX*DIMM];
__device__ float g_XN [NB*TMAX*DIMM];
__device__ float g_QKV[NB*TMAX*3*DIMM];
__device__ float g_OUT[NB*TMAX*DIMM];
__device__ float g_H1 [NB*TMAX*FFD];
__device__ float g_IM [NB*NPATCH*DIMM];
__device__ float g_acls  [NB*HEADS*TMAX];
__device__ float g_vnorm [NB*HEADS*TMAX];
__device__ float g_clsnorm[NB*HEADS];
__device__ float g_imp [NPATCH];
__device__ int   g_keep[TMAX];
__device__ int   g_N, g_T, g_Nnext, g_prune, g_scored, g_skip;
__device__ double g_prevmass;

// ---------------- state init (runs first, every call -> deterministic) ----
__global__ void k_init() {
    g_N = NPATCH; g_T = TMAX;
    g_prevmass = 1.0;
    g_prune = 0; g_scored = 0; g_skip = 0;
}

// ---------------- im2col for the stride-16 patch conv ----------------
__global__ void k_im2col(const float* __restrict__ x) {
    int bn = blockIdx.x;            // b*196 + n
    int b = bn / NPATCH, n = bn % NPATCH;
    int h = n / 14, w = n % 14;
    for (int l = threadIdx.x; l < DIMM; l += 256) {
        int c = l >> 8, p = (l >> 4) & 15, q = l & 15;
        g_IM[(long)bn*DIMM + l] =
            x[(((long)b*3 + c)*224 + h*16 + p)*224 + (w*16 + q)];
    }
}

// ---------------- cls token + positional embedding ----------------
__global__ void k_assemble(const float* __restrict__ cls,
                           const float* __restrict__ pos) {
    int t = blockIdx.x, b = blockIdx.y;
    float* xr = g_X + ((long)b*TMAX + t)*DIMM;
    for (int d = threadIdx.x; d < DIMM; d += 256) {
        if (t == 0) xr[d] = cls[d] + pos[d];
        else        xr[d] += pos[(long)t*DIMM + d];
    }
}

// ---------------- LayerNorm: one block per (b,t), 256 thr, 3 elems/thr ----
// gate: 0=always, 1=only if N>MINTOK (scoring pass), 2=only if !g_skip
__global__ void k_ln(int gate, const float* __restrict__ X, float* __restrict__ Y,
                     const float* __restrict__ w, const float* __restrict__ bb) {
    if (gate == 1 && g_N <= MINTOK) return;
    if (gate == 2 && g_skip)        return;
    int t = blockIdx.x; if (t >= g_T) return;
    int b = blockIdx.y, tid = threadIdx.x;
    const float* x = X + ((long)b*TMAX + t)*DIMM;
    float v0 = x[tid], v1 = x[tid+256], v2 = x[tid+512];
    __shared__ float sd[256];
    sd[tid] = v0 + v1 + v2; __syncthreads();
    for (int o = 128; o > 0; o >>= 1) { if (tid < o) sd[tid] += sd[tid+o]; __syncthreads(); }
    float mu = sd[0] * (1.0f/768.0f);
    __syncthreads();
    float d0 = v0-mu, d1 = v1-mu, d2 = v2-mu;
    sd[tid] = d0*d0 + d1*d1 + d2*d2; __syncthreads();
    for (int o = 128; o > 0; o >>= 1) { if (tid < o) sd[tid] += sd[tid+o]; __syncthreads(); }
    float rs = rsqrtf(sd[0] * (1.0f/768.0f) + 1e-6f);
    float* y = Y + ((long)b*TMAX + t)*DIMM;
    y[tid]     = d0*rs*w[tid]     + bb[tid];
    y[tid+256] = d1*rs*w[tid+256] + bb[tid+256];
    y[tid+512] = d2*rs*w[tid+512] + bb[tid+512];
}

// ---------------- tiled SGEMM: C[M,Nn] = A[M,K] @ W[Nn,K]^T + bias --------
// 64x64 tile, BK=16, 256 threads, 4x4 per thread. Rows bounded by g_T (or fixedM).
// mode: 0=store, 1=residual add in-place, 2=exact GELU
__global__ void k_gemm(int gate,
                       const float* __restrict__ A, long long sAb,
                       const float* __restrict__ W, const float* __restrict__ bias,
                       float* __restrict__ C, long long sCb, int ldc,
                       int K, int Nn, int fixedM, int mode) {
    if (gate == 1 && g_N <= MINTOK) return;
    if (gate == 2 && g_skip)        return;
    int M = (fixedM > 0) ? fixedM : g_T;
    int brow = blockIdx.y * 64;
    if (brow >= M) return;
    int bcol = blockIdx.x * 64;
    const float* Ab = A + (long long)blockIdx.z * sAb;
    float*       Cb = C + (long long)blockIdx.z * sCb;
    int tid = threadIdx.x, tx = tid & 15, ty = tid >> 4;
    __shared__ float As[16][64];
    __shared__ float Ws[16][64];
    float acc[4][4] = {};
    for (int k0 = 0; k0 < K; k0 += 16) {
        #pragma unroll
        for (int l = tid; l < 1024; l += 256) {
            int m = l >> 4, kk = l & 15;
            int gm = brow + m;
            As[kk][m] = (gm < M) ? Ab[(long)gm*K + k0 + kk] : 0.f;
        }
        #pragma unroll
        for (int l = tid; l < 1024; l += 256) {
            int n = l >> 4, kk = l & 15;
            int gn = bcol + n;
            Ws[kk][n] = (gn < Nn) ? W[(long)gn*K + k0 + kk] : 0.f;
        }
        __syncthreads();
        #pragma unroll
        for (int kk = 0; kk < 16; kk++) {
            float a[4], wv[4];
            #pragma unroll
            for (int i = 0; i < 4; i++) a[i]  = As[kk][ty*4 + i];
            #pragma unroll
            for (int j = 0; j < 4; j++) wv[j] = Ws[kk][tx*4 + j];
            #pragma unroll
            for (int i = 0; i < 4; i++)
                #pragma unroll
                for (int j = 0; j < 4; j++)
                    acc[i][j] += a[i] * wv[j];
        }
        __syncthreads();
    }
    #pragma unroll
    for (int i = 0; i < 4; i++) {
        int gm = brow + ty*4 + i; if (gm >= M) continue;
        #pragma unroll
        for (int j = 0; j < 4; j++) {
            int gn = bcol + tx*4 + j; if (gn >= Nn) continue;
            float v = acc[i][j] + bias[gn];
            long idx = (long)gm*ldc + gn;
            if (mode == 1)      v += Cb[idx];
            else if (mode == 2) v = 0.5f * v * (1.0f + erff(v * 0.70710678118654752f));
            Cb[idx] = v;
        }
    }
}

// ---------------- full attention: one block per (b,h,tq), 128 threads ----
__global__ void k_attn() {
    int tq = blockIdx.x; if (tq >= g_T) return;
    int bh = blockIdx.y; int b = bh / HEADS, h = bh % HEADS;
    int tid = threadIdx.x; int T = g_T;
    const float* Qb = g_QKV + (long)b*TMAX*3*DIMM;
    __shared__ float q[64];
    __shared__ float logit[TMAX];
    __shared__ float red[128];
    if (tid < 64) q[tid] = Qb[(long)tq*3*DIMM + h*64 + tid];
    __syncthreads();
    for (int t = tid; t < T; t += 128) {
        const float* kp = Qb + (long)t*3*DIMM + DIMM + h*64;
        float s = 0.f;
        #pragma unroll
        for (int d = 0; d < 64; d++) s += q[d]*kp[d];
        logit[t] = s * SCALE_;
    }
    __syncthreads();
    float m = -1e30f;
    for (int t = tid; t < T; t += 128) m = fmaxf(m, logit[t]);
    red[tid] = m; __syncthreads();
    for (int o = 64; o > 0; o >>= 1) { if (tid < o) red[tid] = fmaxf(red[tid], red[tid+o]); __syncthreads(); }
    float mx = red[0]; __syncthreads();
    float s = 0.f;
    for (int t = tid; t < T; t += 128) { float e = expf(logit[t]-mx); logit[t] = e; s += e; }
    red[tid] = s; __syncthreads();
    for (int o = 64; o > 0; o >>= 1) { if (tid < o) red[tid] += red[tid+o]; __syncthreads(); }
    float inv = 1.0f / red[0];
    __syncthreads();
    int d = tid & 63, half = tid >> 6;
    float acc = 0.f;
    for (int t = half; t < T; t += 2)
        acc += logit[t] * Qb[(long)t*3*DIMM + 2*DIMM + h*64 + d];
    red[tid] = acc; __syncthreads();
    if (half == 0)
        g_OUT[((long)b*TMAX + tq)*DIMM + h*64 + d] = (red[d] + red[d+64]) * inv;
}

// ---------------- scoring: CLS attention, v-norms, cls_out norm ----------
__global__ void k_cls() {
    if (g_N <= MINTOK) return;
    int bh = blockIdx.x; int b = bh / HEADS, h = bh % HEADS;
    int tid = threadIdx.x; int T = g_T;
    const float* Qb = g_QKV + (long)b*TMAX*3*DIMM;
    __shared__ float q[64];
    __shared__ float logit[TMAX];
    __shared__ float red[128];
    if (tid < 64) q[tid] = Qb[h*64 + tid];           // tq = 0 (CLS)
    __syncthreads();
    for (int t = tid; t < T; t += 128) {
        const float* kp = Qb + (long)t*3*DIMM + DIMM   + h*64;
        const float* vp = Qb + (long)t*3*DIMM + 2*DIMM + h*64;
        float s = 0.f, vn = 0.f;
        #pragma unroll
        for (int d = 0; d < 64; d++) { s += q[d]*kp[d]; vn += vp[d]*vp[d]; }
        logit[t] = s * SCALE_;
        g_vnorm[(long)bh*TMAX + t] = sqrtf(vn);
    }
    __syncthreads();
    float m = -1e30f;
    for (int t = tid; t < T; t += 128) m = fmaxf(m, logit[t]);
    red[tid] = m; __syncthreads();
    for (int o = 64; o > 0; o >>= 1) { if (tid < o) red[tid] = fmaxf(red[tid], red[tid+o]); __syncthreads(); }
    float mx = red[0]; __syncthreads();
    float s = 0.f;
    for (int t = tid; t < T; t += 128) { float e = expf(logit[t]-mx); logit[t] = e; s += e; }
    red[tid] = s; __syncthreads();
    for (int o = 64; o > 0; o >>= 1) { if (tid < o) red[tid] += red[tid+o]; __syncthreads(); }
    float inv = 1.0f / red[0];
    __syncthreads();
    for (int t = tid; t < T; t += 128) g_acls[(long)bh*TMAX + t] = logit[t] * inv;
    int d = tid & 63, half = tid >> 6;
    float acc = 0.f;
    for (int t = half; t < T; t += 2)
        acc += logit[t] * Qb[(long)t*3*DIMM + 2*DIMM + h*64 + d];
    red[tid] = acc; __syncthreads();
    if (tid < 64) red[tid] = (red[tid] + red[tid+64]) * inv;   // cls_out[d]
    __syncthreads();
    float co = (tid < 64) ? red[tid] : 0.f;
    __syncthreads();
    red[tid] = co * co; __syncthreads();
    for (int o = 64; o > 0; o >>= 1) { if (tid < o) red[tid] += red[tid+o]; __syncthreads(); }
    if (tid == 0) g_clsnorm[bh] = sqrtf(red[0]);
}

// ---------------- rho / imp / mass / keep_ratio (1 block) ----------------
__global__ void k_reduce() {
    if (g_N <= MINTOK) return;
    int tid = threadIdx.x; int N = g_N;
    __shared__ float sh[256];
    __shared__ float imp_s[NPATCH];
    float r = (tid < 96) ? g_clsnorm[tid] : 0.f;
    sh[tid] = r; __syncthreads();
    for (int o = 128; o > 0; o >>= 1) { if (tid < o) sh[tid] += sh[tid+o]; __syncthreads(); }
    float rho = sh[0] * (1.0f/96.0f);
    __syncthreads();
    for (int i = tid; i < N; i += 256) {
        int t = i + 1; float s = 0.f;
        for (int bh = 0; bh < 96; bh++)
            s += g_acls[(long)bh*TMAX + t] * g_vnorm[(long)bh*TMAX + t];
        imp_s[i] = s * (1.0f/96.0f);
    }
    __syncthreads();
    float loc = 0.f;
    for (int i = tid; i < N; i += 256) loc += imp_s[i];
    sh[tid] = loc; __syncthreads();
    for (int o = 128; o > 0; o >>= 1) { if (tid < o) sh[tid] += sh[tid+o]; __syncthreads(); }
    float mass = sh[0];
    float dv = (float)((double)mass + 1e-6);          // matches jnp f32 divide by (mass+EPS)
    for (int i = tid; i < N; i += 256) g_imp[i] = imp_s[i] / dv;
    if (tid == 0) {
        double km = (double)mass / (g_prevmass + 1e-6) + 1e-6;
        double kr = 1.0 - 0.01 * (double)rho / km;    // Python-double arithmetic
        kr = fmin(1.0, fmax(0.0, kr));
        int Nn = (int)((double)N * kr);               // int() truncation
        if (Nn < MINTOK) Nn = MINTOK;
        g_Nnext = Nn;
        g_prune = (Nn < N) ? 1 : 0;
        g_scored = 1;
        g_prevmass = (double)mass;
    }
}

// ---------------- top-k by rank (== top_k + ascending sort, ties by idx) --
__global__ void k_topk() {
    if (!g_prune) return;
    int tid = threadIdx.x; int N = g_N, Nn = g_Nnext;
    __shared__ unsigned char keepf[NPATCH];
    for (int i = tid; i < N; i += 256) {
        float vi = g_imp[i]; int rank = 0;
        for (int j = 0; j < N; j++) {
            float vj = g_imp[j];
            rank += (vj > vi) || (vj == vi && j < i);
        }
        keepf[i] = (rank < Nn) ? 1 : 0;
    }
    __syncthreads();
    if (tid == 0) {
        g_keep[0] = 0; int c = 1;
        for (int i = 0; i < N; i++) if (keepf[i]) g_keep[c++] = i + 1;
    }
}

__global__ void k_gather() {
    if (!g_prune) return;
    int Tn = g_Nnext + 1;
    int j = blockIdx.x; if (j >= Tn) return;
    int b = blockIdx.y; int src = g_keep[j];
    const float* s = g_X  + ((long)b*TMAX + src)*DIMM;
    float*       d = g_X2 + ((long)b*TMAX + j  )*DIMM;
    for (int e = threadIdx.x; e < DIMM; e += 256) d[e] = s[e];
}

__global__ void k_copyback() {
    if (!g_prune) return;
    int Tn = g_Nnext + 1;
    int j = blockIdx.x; if (j >= Tn) return;
    int b = blockIdx.y;
    const float* s = g_X2 + ((long)b*TMAX + j)*DIMM;
    float*       d = g_X  + ((long)b*TMAX + j)*DIMM;
    for (int e = threadIdx.x; e < DIMM; e += 256) d[e] = s[e];
}

__global__ void k_commit() {
    if (threadIdx.x == 0) {
        g_skip = (g_scored && !g_prune) ? 1 : 0;   // reuse scoring LN/QKV when unpruned
        if (g_prune) { g_N = g_Nnext; g_T = g_N + 1; }
        g_prune = 0; g_scored = 0;
    }
}

// ---------------- classifier head: grid=1000, 8 warps = 8 batch rows -----
__global__ void k_head(const float* __restrict__ hw, const float* __restrict__ hb,
                       float* __restrict__ out) {
    int c = blockIdx.x;
    int w = threadIdx.x >> 5, lane = threadIdx.x & 31;
    const float* xn = g_XN + (long)w*TMAX*DIMM;      // b = warp, token 0
    const float* wr = hw + (long)c*DIMM;
    float s = 0.f;
    for (int d = lane; d < DIMM; d += 32) s += xn[d]*wr[d];
    for (int o = 16; o > 0; o >>= 1) s += __shfl_down_sync(0xffffffffu, s, o);
    if (lane == 0) out[w*NCLS + c] = s + hb[c];
}

// ---------------- host launcher ----------------
extern "C" void kernel_launch(void* const* d_in, const int* in_sizes, int n_in,
                              void* d_out, int out_size) {
    const float* x      = (const float*)d_in[0];
    const float* conv_w = (const float*)d_in[1];
    const float* conv_b = (const float*)d_in[2];
    const float* cls    = (const float*)d_in[3];
    const float* pos    = (const float*)d_in[4];
    const float* ln1w   = (const float*)d_in[5];
    const float* ln1b   = (const float*)d_in[6];
    const float* qkvw   = (const float*)d_in[7];
    const float* qkvb   = (const float*)d_in[8];
    const float* projw  = (const float*)d_in[9];
    const float* projb  = (const float*)d_in[10];
    const float* ln2w   = (const float*)d_in[11];
    const float* ln2b   = (const float*)d_in[12];
    const float* fc1w   = (const float*)d_in[13];
    const float* fc1b   = (const float*)d_in[14];
    const float* fc2w   = (const float*)d_in[15];
    const float* fc2b   = (const float*)d_in[16];
    const float* lnfw   = (const float*)d_in[17];
    const float* lnfb   = (const float*)d_in[18];
    const float* headw  = (const float*)d_in[19];
    const float* headb  = (const float*)d_in[20];
    float* out = (float*)d_out;

    void *vX, *vX2, *vXN, *vQKV, *vOUT, *vH1, *vIM;
    cudaGetSymbolAddress(&vX,   g_X);
    cudaGetSymbolAddress(&vX2,  g_X2);
    cudaGetSymbolAddress(&vXN,  g_XN);
    cudaGetSymbolAddress(&vQKV, g_QKV);
    cudaGetSymbolAddress(&vOUT, g_OUT);
    cudaGetSymbolAddress(&vH1,  g_H1);
    cudaGetSymbolAddress(&vIM,  g_IM);
    float* pX   = (float*)vX;
    float* pXN  = (float*)vXN;
    float* pQKV = (float*)vQKV;
    float* pOUT = (float*)vOUT;
    float* pH1  = (float*)vH1;
    float* pIM  = (float*)vIM;
    (void)vX2; (void)in_sizes; (void)n_in; (void)out_size;

    const long long sX  = (long long)TMAX*DIMM;
    const long long sQ  = (long long)TMAX*3*DIMM;
    const long long sH  = (long long)TMAX*FFD;

    k_init<<<1,1>>>();

    // patch embed
    k_im2col<<<NB*NPATCH, 256>>>(x);
    k_gemm<<<dim3(12,4,NB), 256>>>(0, pIM, (long long)NPATCH*DIMM,
                                   conv_w, conv_b,
                                   pX + DIMM, sX, DIMM,
                                   DIMM, DIMM, NPATCH, 0);
    k_assemble<<<dim3(TMAX,NB), 256>>>(cls, pos);

    for (int i = 0; i < 12; i++) {
        const float* l1w = ln1w + (long)i*DIMM;
        const float* l1b = ln1b + (long)i*DIMM;
        const float* qw  = qkvw + (long)i*3*DIMM*DIMM;
        const float* qb  = qkvb + (long)i*3*DIMM;
        const float* pw  = projw + (long)i*DIMM*DIMM;
        const float* pb  = projb + (long)i*DIMM;
        const float* l2w = ln2w + (long)i*DIMM;
        const float* l2b = ln2b + (long)i*DIMM;
        const float* f1w = fc1w + (long)i*FFD*DIMM;
        const float* f1b = fc1b + (long)i*FFD;
        const float* f2w = fc2w + (long)i*DIMM*FFD;
        const float* f2b = fc2b + (long)i*DIMM;

        // ---- scoring pass (gated on N > MIN_TOKENS) ----
        k_ln  <<<dim3(TMAX,NB), 256>>>(1, pX, pXN, l1w, l1b);
        k_gemm<<<dim3(36,4,NB), 256>>>(1, pXN, sX, qw, qb, pQKV, sQ, 3*DIMM,
                                       DIMM, 3*DIMM, 0, 0);
        k_cls   <<<NB*HEADS, 128>>>();
        k_reduce<<<1, 256>>>();
        k_topk  <<<1, 256>>>();
        k_gather  <<<dim3(TMAX,NB), 256>>>();
        k_copyback<<<dim3(TMAX,NB), 256>>>();
        k_commit<<<1,1>>>();

        // ---- main block (LN/QKV skipped via g_skip when identical) ----
        k_ln  <<<dim3(TMAX,NB), 256>>>(2, pX, pXN, l1w, l1b);
        k_gemm<<<dim3(36,4,NB), 256>>>(2, pXN, sX, qw, qb, pQKV, sQ, 3*DIMM,
                                       DIMM, 3*DIMM, 0, 0);
        k_attn<<<dim3(TMAX, NB*HEADS), 128>>>();
        k_gemm<<<dim3(12,4,NB), 256>>>(0, pOUT, sX, pw, pb, pX, sX, DIMM,
                                       DIMM, DIMM, 0, 1);
        k_ln  <<<dim3(TMAX,NB), 256>>>(0, pX, pXN, l2w, l2b);
        k_gemm<<<dim3(48,4,NB), 256>>>(0, pXN, sX, f1w, f1b, pH1, sH, FFD,
                                       DIMM, FFD, 0, 2);
        k_gemm<<<dim3(12,4,NB), 256>>>(0, pH1, sH, f2w, f2b, pX, sX, DIMM,
                                       FFD, DIMM, 0, 1);
    }

    // final LN (token 0 only needed, LN is per-token) + head
    k_ln<<<dim3(1,NB), 256>>>(0, pX, pXN, lnfw, lnfb);
    k_head<<<NCLS, 256>>>(headw, headb, out);
}

// round 2
// speedup vs baseline: 1.3533x; 1.3533x over previous
#include <cuda_runtime.h>
#include <math.h>

// ---------------- problem constants ----------------
#define NB      8
#define HEADS   12
#define DIMM    768
#define HDD     64
#define TMAX    197
#define NPATCH  196
#define FFD     3072
#define NCLS    1000
#define MINTOK  16
#define SCALE_  0.125f   // HD^-0.5 = 1/8

// ---------------- device scratch (no allocation allowed) ----------------
__device__ float g_X  [NB*TMAX*DIMM];
__device__ float g_X2 [NB*TMAX*DIMM];
__device__ float g_XN [NB*TMAX*DIMM];
__device__ float g_QKV[NB*TMAX*3*DIMM];
__device__ float g_OUT[NB*TMAX*DIMM];
__device__ float g_H1 [NB*TMAX*FFD];
__device__ float g_IM [NB*NPATCH*DIMM];
__device__ float g_acls  [NB*HEADS*TMAX];
__device__ float g_vnorm [NB*HEADS*TMAX];
__device__ float g_clsnorm[NB*HEADS];
__device__ float g_imp [NPATCH];
__device__ int   g_keep[TMAX];
__device__ int   g_N, g_T, g_Nnext, g_prune, g_scored, g_skip;
__device__ double g_prevmass;

// ---------------- state init ----------------
__global__ void k_init() {
    g_N = NPATCH; g_T = TMAX;
    g_prevmass = 1.0;
    g_prune = 0; g_scored = 0; g_skip = 0;
}

// ---------------- im2col for the stride-16 patch conv ----------------
__global__ void k_im2col(const float* __restrict__ x) {
    int bn = blockIdx.x;            // b*196 + n
    int b = bn / NPATCH, n = bn % NPATCH;
    int h = n / 14, w = n % 14;
    for (int l = threadIdx.x; l < DIMM; l += 256) {
        int c = l >> 8, p = (l >> 4) & 15, q = l & 15;
        g_IM[(long)bn*DIMM + l] =
            x[(((long)b*3 + c)*224 + h*16 + p)*224 + (w*16 + q)];
    }
}

// ---------------- cls token + positional embedding ----------------
__global__ void k_assemble(const float* __restrict__ cls,
                           const float* __restrict__ pos) {
    int t = blockIdx.x, b = blockIdx.y;
    float* xr = g_X + ((long)b*TMAX + t)*DIMM;
    for (int d = threadIdx.x; d < DIMM; d += 256) {
        if (t == 0) xr[d] = cls[d] + pos[d];
        else        xr[d] += pos[(long)t*DIMM + d];
    }
}

// ---------------- LayerNorm ----------------
// gate: 0=always, 1=only if N>MINTOK (scoring pass), 2=only if !g_skip
__global__ void k_ln(int gate, const float* __restrict__ X, float* __restrict__ Y,
                     const float* __restrict__ w, const float* __restrict__ bb) {
    if (gate == 1 && g_N <= MINTOK) return;
    if (gate == 2 && g_skip)        return;
    int t = blockIdx.x; if (t >= g_T) return;
    int b = blockIdx.y, tid = threadIdx.x;
    const float* x = X + ((long)b*TMAX + t)*DIMM;
    float v0 = x[tid], v1 = x[tid+256], v2 = x[tid+512];
    __shared__ float sd[256];
    sd[tid] = v0 + v1 + v2; __syncthreads();
    for (int o = 128; o > 0; o >>= 1) { if (tid < o) sd[tid] += sd[tid+o]; __syncthreads(); }
    float mu = sd[0] * (1.0f/768.0f);
    __syncthreads();
    float d0 = v0-mu, d1 = v1-mu, d2 = v2-mu;
    sd[tid] = d0*d0 + d1*d1 + d2*d2; __syncthreads();
    for (int o = 128; o > 0; o >>= 1) { if (tid < o) sd[tid] += sd[tid+o]; __syncthreads(); }
    float rs = rsqrtf(sd[0] * (1.0f/768.0f) + 1e-6f);
    float* y = Y + ((long)b*TMAX + t)*DIMM;
    y[tid]     = d0*rs*w[tid]     + bb[tid];
    y[tid+256] = d1*rs*w[tid+256] + bb[tid+256];
    y[tid+512] = d2*rs*w[tid+512] + bb[tid+512];
}

// ---------------- 128x128x16 double-buffered SGEMM --------------------
// C[M,Nn] = A[M,K] @ W[Nn,K]^T + bias. Requires: K%16==0, Nn%128==0,
// gridDim.x == Nn/128. Rows bounded by g_T (or fixedM).
// mode: 0=store, 1=residual add in-place, 2=exact GELU
__global__ void __launch_bounds__(256, 2)
k_gemm(int gate,
       const float* __restrict__ A, long long sAb,
       const float* __restrict__ W, const float* __restrict__ bias,
       float* __restrict__ C, long long sCb, int ldc,
       int K, int Nn, int fixedM, int mode) {
    if (gate == 1 && g_N <= MINTOK) return;
    if (gate == 2 && g_skip)        return;
    int M = (fixedM > 0) ? fixedM : g_T;
    int brow = blockIdx.y * 128;
    if (brow >= M) return;
    int bcol = blockIdx.x * 128;
    const float* Ab = A + (long long)blockIdx.z * sAb;
    float*       Cb = C + (long long)blockIdx.z * sCb;

    __shared__ __align__(16) float As[2][16][132];
    __shared__ __align__(16) float Ws[2][16][132];

    int tid = threadIdx.x;
    int tx  = tid & 15, ty = tid >> 4;          // microtile coords
    int lrow = tid >> 1;                         // 0..127 (tile row / tile col)
    int lkq  = (tid & 1) * 8;                    // k sub-offset 0 or 8

    int gmA = brow + lrow;
    bool aval = (gmA < M);
    const float* aG = Ab + (long long)gmA * K + lkq;
    const float* wG = W  + (long long)(bcol + lrow) * K + lkq;

    float acc[8][8];
    #pragma unroll
    for (int i = 0; i < 8; i++)
        #pragma unroll
        for (int j = 0; j < 8; j++) acc[i][j] = 0.f;

    float4 ra0, ra1, rw0, rw1;
    const float4 z4 = make_float4(0.f,0.f,0.f,0.f);

    // prefetch tile 0
    if (aval) { ra0 = *(const float4*)(aG);     ra1 = *(const float4*)(aG + 4); }
    else      { ra0 = z4; ra1 = z4; }
    rw0 = *(const float4*)(wG);  rw1 = *(const float4*)(wG + 4);

    {   // store tile 0
        float av[8] = {ra0.x,ra0.y,ra0.z,ra0.w,ra1.x,ra1.y,ra1.z,ra1.w};
        float wv[8] = {rw0.x,rw0.y,rw0.z,rw0.w,rw1.x,rw1.y,rw1.z,rw1.w};
        #pragma unroll
        for (int j = 0; j < 8; j++) { As[0][lkq+j][lrow] = av[j]; Ws[0][lkq+j][lrow] = wv[j]; }
    }
    __syncthreads();

    int ntiles = K >> 4;
    int buf = 0;
    for (int t = 0; t < ntiles; t++) {
        bool more = (t + 1 < ntiles);
        if (more) {
            int nk = (t + 1) << 4;
            if (aval) { ra0 = *(const float4*)(aG + nk); ra1 = *(const float4*)(aG + nk + 4); }
            rw0 = *(const float4*)(wG + nk);  rw1 = *(const float4*)(wG + nk + 4);
        }
        #pragma unroll
        for (int kk = 0; kk < 16; kk++) {
            float4 x0 = *(const float4*)&As[buf][kk][ty*8];
            float4 x1 = *(const float4*)&As[buf][kk][ty*8 + 4];
            float4 y0 = *(const float4*)&Ws[buf][kk][tx*8];
            float4 y1 = *(const float4*)&Ws[buf][kk][tx*8 + 4];
            float a[8] = {x0.x,x0.y,x0.z,x0.w,x1.x,x1.y,x1.z,x1.w};
            float b[8] = {y0.x,y0.y,y0.z,y0.w,y1.x,y1.y,y1.z,y1.w};
            #pragma unroll
            for (int i = 0; i < 8; i++)
                #pragma unroll
                for (int j = 0; j < 8; j++)
                    acc[i][j] = fmaf(a[i], b[j], acc[i][j]);
        }
        if (more) {
            buf ^= 1;
            float av[8] = {ra0.x,ra0.y,ra0.z,ra0.w,ra1.x,ra1.y,ra1.z,ra1.w};
            float wv[8] = {rw0.x,rw0.y,rw0.z,rw0.w,rw1.x,rw1.y,rw1.z,rw1.w};
            #pragma unroll
            for (int j = 0; j < 8; j++) { As[buf][lkq+j][lrow] = av[j]; Ws[buf][lkq+j][lrow] = wv[j]; }
            __syncthreads();
        }
    }

    #pragma unroll
    for (int i = 0; i < 8; i++) {
        int gm = brow + ty*8 + i; if (gm >= M) continue;
        #pragma unroll
        for (int j = 0; j < 8; j++) {
            int gn = bcol + tx*8 + j;
            float v = acc[i][j] + bias[gn];
            long long idx = (long long)gm*ldc + gn;
            if (mode == 1)      v += Cb[idx];
            else if (mode == 2) v = 0.5f * v * (1.0f + erff(v * 0.70710678118654752f));
            Cb[idx] = v;
        }
    }
}

// ---------------- full attention: one block per (b,h,tq), 128 threads ----
__global__ void k_attn() {
    int tq = blockIdx.x; if (tq >= g_T) return;
    int bh = blockIdx.y; int b = bh / HEADS, h = bh % HEADS;
    int tid = threadIdx.x; int T = g_T;
    const float* Qb = g_QKV + (long)b*TMAX*3*DIMM;
    __shared__ float q[64];
    __shared__ float logit[TMAX];
    __shared__ float red[128];
    if (tid < 64) q[tid] = Qb[(long)tq*3*DIMM + h*64 + tid];
    __syncthreads();
    for (int t = tid; t < T; t += 128) {
        const float* kp = Qb + (long)t*3*DIMM + DIMM + h*64;
        float s = 0.f;
        #pragma unroll
        for (int d = 0; d < 64; d++) s += q[d]*kp[d];
        logit[t] = s * SCALE_;
    }
    __syncthreads();
    float m = -1e30f;
    for (int t = tid; t < T; t += 128) m = fmaxf(m, logit[t]);
    red[tid] = m; __syncthreads();
    for (int o = 64; o > 0; o >>= 1) { if (tid < o) red[tid] = fmaxf(red[tid], red[tid+o]); __syncthreads(); }
    float mx = red[0]; __syncthreads();
    float s = 0.f;
    for (int t = tid; t < T; t += 128) { float e = expf(logit[t]-mx); logit[t] = e; s += e; }
    red[tid] = s; __syncthreads();
    for (int o = 64; o > 0; o >>= 1) { if (tid < o) red[tid] += red[tid+o]; __syncthreads(); }
    float inv = 1.0f / red[0];
    __syncthreads();
    int d = tid & 63, half = tid >> 6;
    float acc = 0.f;
    for (int t = half; t < T; t += 2)
        acc += logit[t] * Qb[(long)t*3*DIMM + 2*DIMM + h*64 + d];
    red[tid] = acc; __syncthreads();
    if (half == 0)
        g_OUT[((long)b*TMAX + tq)*DIMM + h*64 + d] = (red[d] + red[d+64]) * inv;
}

// ---------------- scoring: CLS attention, v-norms, cls_out norm ----------
__global__ void k_cls() {
    if (g_N <= MINTOK) return;
    int bh = blockIdx.x; int b = bh / HEADS, h = bh % HEADS;
    int tid = threadIdx.x; int T = g_T;
    const float* Qb = g_QKV + (long)b*TMAX*3*DIMM;
    __shared__ float q[64];
    __shared__ float logit[TMAX];
    __shared__ float red[128];
    if (tid < 64) q[tid] = Qb[h*64 + tid];           // tq = 0 (CLS)
    __syncthreads();
    for (int t = tid; t < T; t += 128) {
        const float* kp = Qb + (long)t*3*DIMM + DIMM   + h*64;
        const float* vp = Qb + (long)t*3*DIMM + 2*DIMM + h*64;
        float s = 0.f, vn = 0.f;
        #pragma unroll
        for (int d = 0; d < 64; d++) { s += q[d]*kp[d]; vn += vp[d]*vp[d]; }
        logit[t] = s * SCALE_;
        g_vnorm[(long)bh*TMAX + t] = sqrtf(vn);
    }
    __syncthreads();
    float m = -1e30f;
    for (int t = tid; t < T; t += 128) m = fmaxf(m, logit[t]);
    red[tid] = m; __syncthreads();
    for (int o = 64; o > 0; o >>= 1) { if (tid < o) red[tid] = fmaxf(red[tid], red[tid+o]); __syncthreads(); }
    float mx = red[0]; __syncthreads();
    float s = 0.f;
    for (int t = tid; t < T; t += 128) { float e = expf(logit[t]-mx); logit[t] = e; s += e; }
    red[tid] = s; __syncthreads();
    for (int o = 64; o > 0; o >>= 1) { if (tid < o) red[tid] += red[tid+o]; __syncthreads(); }
    float inv = 1.0f / red[0];
    __syncthreads();
    for (int t = tid; t < T; t += 128) g_acls[(long)bh*TMAX + t] = logit[t] * inv;
    int d = tid & 63, half = tid >> 6;
    float acc = 0.f;
    for (int t = half; t < T; t += 2)
        acc += logit[t] * Qb[(long)t*3*DIMM + 2*DIMM + h*64 + d];
    red[tid] = acc; __syncthreads();
    if (tid < 64) red[tid] = (red[tid] + red[tid+64]) * inv;   // cls_out[d]
    __syncthreads();
    float co = (tid < 64) ? red[tid] : 0.f;
    __syncthreads();
    red[tid] = co * co; __syncthreads();
    for (int o = 64; o > 0; o >>= 1) { if (tid < o) red[tid] += red[tid+o]; __syncthreads(); }
    if (tid == 0) g_clsnorm[bh] = sqrtf(red[0]);
}

// ---------------- rho / imp / mass / keep_ratio (1 block) ----------------
__global__ void k_reduce() {
    if (g_N <= MINTOK) return;
    int tid = threadIdx.x; int N = g_N;
    __shared__ float sh[256];
    __shared__ float imp_s[NPATCH];
    float r = (tid < 96) ? g_clsnorm[tid] : 0.f;
    sh[tid] = r; __syncthreads();
    for (int o = 128; o > 0; o >>= 1) { if (tid < o) sh[tid] += sh[tid+o]; __syncthreads(); }
    float rho = sh[0] * (1.0f/96.0f);
    __syncthreads();
    for (int i = tid; i < N; i += 256) {
        int t = i + 1; float s = 0.f;
        for (int bh = 0; bh < 96; bh++)
            s += g_acls[(long)bh*TMAX + t] * g_vnorm[(long)bh*TMAX + t];
        imp_s[i] = s * (1.0f/96.0f);
    }
    __syncthreads();
    float loc = 0.f;
    for (int i = tid; i < N; i += 256) loc += imp_s[i];
    sh[tid] = loc; __syncthreads();
    for (int o = 128; o > 0; o >>= 1) { if (tid < o) sh[tid] += sh[tid+o]; __syncthreads(); }
    float mass = sh[0];
    float dv = (float)((double)mass + 1e-6);
    for (int i = tid; i < N; i += 256) g_imp[i] = imp_s[i] / dv;
    if (tid == 0) {
        double km = (double)mass / (g_prevmass + 1e-6) + 1e-6;
        double kr = 1.0 - 0.01 * (double)rho / km;
        kr = fmin(1.0, fmax(0.0, kr));
        int Nn = (int)((double)N * kr);
        if (Nn < MINTOK) Nn = MINTOK;
        g_Nnext = Nn;
        g_prune = (Nn < N) ? 1 : 0;
        g_scored = 1;
        g_prevmass = (double)mass;
    }
}

// ---------------- top-k by rank ----------------
__global__ void k_topk() {
    if (!g_prune) return;
    int tid = threadIdx.x; int N = g_N, Nn = g_Nnext;
    __shared__ unsigned char keepf[NPATCH];
    for (int i = tid; i < N; i += 256) {
        float vi = g_imp[i]; int rank = 0;
        for (int j = 0; j < N; j++) {
            float vj = g_imp[j];
            rank += (vj > vi) || (vj == vi && j < i);
        }
        keepf[i] = (rank < Nn) ? 1 : 0;
    }
    __syncthreads();
    if (tid == 0) {
        g_keep[0] = 0; int c = 1;
        for (int i = 0; i < N; i++) if (keepf[i]) g_keep[c++] = i + 1;
    }
}

__global__ void k_gather() {
    if (!g_prune) return;
    int Tn = g_Nnext + 1;
    int j = blockIdx.x; if (j >= Tn) return;
    int b = blockIdx.y; int src = g_keep[j];
    const float* s = g_X  + ((long)b*TMAX + src)*DIMM;
    float*       d = g_X2 + ((long)b*TMAX + j  )*DIMM;
    for (int e = threadIdx.x; e < DIMM; e += 256) d[e] = s[e];
}

__global__ void k_copyback() {
    if (!g_prune) return;
    int Tn = g_Nnext + 1;
    int j = blockIdx.x; if (j >= Tn) return;
    int b = blockIdx.y;
    const float* s = g_X2 + ((long)b*TMAX + j)*DIMM;
    float*       d = g_X  + ((long)b*TMAX + j)*DIMM;
    for (int e = threadIdx.x; e < DIMM; e += 256) d[e] = s[e];
}

__global__ void k_commit() {
    if (threadIdx.x == 0) {
        g_skip = (g_scored && !g_prune) ? 1 : 0;
        if (g_prune) { g_N = g_Nnext; g_T = g_N + 1; }
        g_prune = 0; g_scored = 0;
    }
}

// ---------------- classifier head ----------------
__global__ void k_head(const float* __restrict__ hw, const float* __restrict__ hb,
                       float* __restrict__ out) {
    int c = blockIdx.x;
    int w = threadIdx.x >> 5, lane = threadIdx.x & 31;
    const float* xn = g_XN + (long)w*TMAX*DIMM;
    const float* wr = hw + (long)c*DIMM;
    float s = 0.f;
    for (int d = lane; d < DIMM; d += 32) s += xn[d]*wr[d];
    for (int o = 16; o > 0; o >>= 1) s += __shfl_down_sync(0xffffffffu, s, o);
    if (lane == 0) out[w*NCLS + c] = s + hb[c];
}

// ---------------- host launcher ----------------
extern "C" void kernel_launch(void* const* d_in, const int* in_sizes, int n_in,
                              void* d_out, int out_size) {
    const float* x      = (const float*)d_in[0];
    const float* conv_w = (const float*)d_in[1];
    const float* conv_b = (const float*)d_in[2];
    const float* cls    = (const float*)d_in[3];
    const float* pos    = (const float*)d_in[4];
    const float* ln1w   = (const float*)d_in[5];
    const float* ln1b   = (const float*)d_in[6];
    const float* qkvw   = (const float*)d_in[7];
    const float* qkvb   = (const float*)d_in[8];
    const float* projw  = (const float*)d_in[9];
    const float* projb  = (const float*)d_in[10];
    const float* ln2w   = (const float*)d_in[11];
    const float* ln2b   = (const float*)d_in[12];
    const float* fc1w   = (const float*)d_in[13];
    const float* fc1b   = (const float*)d_in[14];
    const float* fc2w   = (const float*)d_in[15];
    const float* fc2b   = (const float*)d_in[16];
    const float* lnfw   = (const float*)d_in[17];
    const float* lnfb   = (const float*)d_in[18];
    const float* headw  = (const float*)d_in[19];
    const float* headb  = (const float*)d_in[20];
    float* out = (float*)d_out;

    void *vX, *vXN, *vQKV, *vOUT, *vH1, *vIM;
    cudaGetSymbolAddress(&vX,   g_X);
    cudaGetSymbolAddress(&vXN,  g_XN);
    cudaGetSymbolAddress(&vQKV, g_QKV);
    cudaGetSymbolAddress(&vOUT, g_OUT);
    cudaGetSymbolAddress(&vH1,  g_H1);
    cudaGetSymbolAddress(&vIM,  g_IM);
    float* pX   = (float*)vX;
    float* pXN  = (float*)vXN;
    float* pQKV = (float*)vQKV;
    float* pOUT = (float*)vOUT;
    float* pH1  = (float*)vH1;
    float* pIM  = (float*)vIM;
    (void)in_sizes; (void)n_in; (void)out_size;

    const long long sX  = (long long)TMAX*DIMM;
    const long long sQ  = (long long)TMAX*3*DIMM;
    const long long sH  = (long long)TMAX*FFD;

    k_init<<<1,1>>>();

    // patch embed
    k_im2col<<<NB*NPATCH, 256>>>(x);
    k_gemm<<<dim3(6,2,NB), 256>>>(0, pIM, (long long)NPATCH*DIMM,
                                  conv_w, conv_b,
                                  pX + DIMM, sX, DIMM,
                                  DIMM, DIMM, NPATCH, 0);
    k_assemble<<<dim3(TMAX,NB), 256>>>(cls, pos);

    for (int i = 0; i < 12; i++) {
        const float* l1w = ln1w + (long)i*DIMM;
        const float* l1b = ln1b + (long)i*DIMM;
        const float* qw  = qkvw + (long)i*3*DIMM*DIMM;
        const float* qb  = qkvb + (long)i*3*DIMM;
        const float* pw  = projw + (long)i*DIMM*DIMM;
        const float* pb  = projb + (long)i*DIMM;
        const float* l2w = ln2w + (long)i*DIMM;
        const float* l2b = ln2b + (long)i*DIMM;
        const float* f1w = fc1w + (long)i*FFD*DIMM;
        const float* f1b = fc1b + (long)i*FFD;
        const float* f2w = fc2w + (long)i*DIMM*FFD;
        const float* f2b = fc2b + (long)i*DIMM;

        // ---- scoring pass (gated on N > MIN_TOKENS) ----
        k_ln  <<<dim3(TMAX,NB), 256>>>(1, pX, pXN, l1w, l1b);
        k_gemm<<<dim3(18,2,NB), 256>>>(1, pXN, sX, qw, qb, pQKV, sQ, 3*DIMM,
                                       DIMM, 3*DIMM, 0, 0);
        k_cls   <<<NB*HEADS, 128>>>();
        k_reduce<<<1, 256>>>();
        k_topk  <<<1, 256>>>();
        k_gather  <<<dim3(TMAX,NB), 256>>>();
        k_copyback<<<dim3(TMAX,NB), 256>>>();
        k_commit<<<1,1>>>();

        // ---- main block (LN/QKV skipped via g_skip when identical) ----
        k_ln  <<<dim3(TMAX,NB), 256>>>(2, pX, pXN, l1w, l1b);
        k_gemm<<<dim3(18,2,NB), 256>>>(2, pXN, sX, qw, qb, pQKV, sQ, 3*DIMM,
                                       DIMM, 3*DIMM, 0, 0);
        k_attn<<<dim3(TMAX, NB*HEADS), 128>>>();
        k_gemm<<<dim3(6,2,NB), 256>>>(0, pOUT, sX, pw, pb, pX, sX, DIMM,
                                      DIMM, DIMM, 0, 1);
        k_ln  <<<dim3(TMAX,NB), 256>>>(0, pX, pXN, l2w, l2b);
        k_gemm<<<dim3(24,2,NB), 256>>>(0, pXN, sX, f1w, f1b, pH1, sH, FFD,
                                       DIMM, FFD, 0, 2);
        k_gemm<<<dim3(6,2,NB), 256>>>(0, pH1, sH, f2w, f2b, pX, sX, DIMM,
                                      FFD, DIMM, 0, 1);
    }

    // final LN (token 0 only needed) + head
    k_ln<<<dim3(1,NB), 256>>>(0, pX, pXN, lnfw, lnfb);
    k_head<<<NCLS, 256>>>(headw, headb, out);
}